// round 10
// baseline (speedup 1.0000x reference)
#include <cuda_runtime.h>
#include <cstdint>

#define NB   64
#define NT   1024
#define NIN  256
#define NH   512
#define NTHB 512     // step kernel threads
#define NCTA 128     // 4 batch-groups x 32 col-groups
#define NBG  4       // batch groups
#define NCG  32      // col groups (producers) per batch group

#define RB 20        // red per-col stride (floats)
#define RC 320       // red per-kt stride (16*RB)

// smem floats: wd 16384 (64KB as u64) + frs 8192 + red 5120
#define SM_FRS 16384
#define SM_RED (16384 + 8192)
#define SMEM_FLOATS (SM_RED + 16 * RC)
#define SMEM_BYTES (SMEM_FLOATS * 4)

// ---------------- device globals (scratch; no allocations allowed) ----------
// one flag per 128B L2 line (R8 lesson: packed flags -> hot-line collapse)
__device__ unsigned g_flags2[NBG][NCG][32];
// fr state: [buf][bgrp][k][16 batches]  -> contiguous per group
__device__ float    g_fr2[2][NBG][NH][16];

__global__ void init_kernel() {
    int i = blockIdx.x * blockDim.x + threadIdx.x;   // 4096 words
    ((unsigned*)g_flags2)[i] = 0u;
}

// ---------------- helpers -----------------------------------------------------
__device__ __forceinline__ uint64_t pk2(float x, float y) {
    uint64_t d; asm("mov.b64 %0, {%1, %2};" : "=l"(d) : "f"(x), "f"(y)); return d;
}
__device__ __forceinline__ uint64_t fma2(uint64_t a, uint64_t b, uint64_t c) {
    uint64_t d; asm("fma.rn.f32x2 %0, %1, %2, %3;" : "=l"(d) : "l"(a), "l"(b), "l"(c)); return d;
}
// acquire poll load (strong, gpu scope)
__device__ __forceinline__ unsigned ld_acq(const unsigned* p) {
    unsigned v;
    asm volatile("ld.acquire.gpu.global.u32 %0, [%1];" : "=r"(v) : "l"(p) : "memory");
    return v;
}
// release flag store (strong, gpu scope)
__device__ __forceinline__ void st_rel(unsigned* p, unsigned v) {
    asm volatile("st.release.gpu.global.u32 [%0], %1;" :: "l"(p), "r"(v) : "memory");
}
// volatile staging load: cannot be compiler-reordered across the volatile poll
__device__ __forceinline__ float4 ldcg_v4(const float4* p) {
    float4 v;
    asm volatile("ld.global.cg.v4.f32 {%0, %1, %2, %3}, [%4];"
                 : "=f"(v.x), "=f"(v.y), "=f"(v.z), "=f"(v.w) : "l"(p) : "memory");
    return v;
}

// ---------------- Phase A: v_in = x @ W_in + b_in -> d_out -------------------
#define BM 64
#define BN 64
#define BK 16

__global__ __launch_bounds__(256) void gemm_vin(const float* __restrict__ A,
                                                const float* __restrict__ Bm,
                                                const float* __restrict__ bias,
                                                float* __restrict__ C) {
    __shared__ float As[BK][BM + 4];
    __shared__ float Bs[BK][BN];
    const int tid = threadIdx.x;
    const int m0 = blockIdx.y * BM;
    const int n0 = blockIdx.x * BN;
    const int tx = tid & 15;
    const int ty = tid >> 4;

    float acc[4][4];
#pragma unroll
    for (int i = 0; i < 4; ++i)
#pragma unroll
        for (int j = 0; j < 4; ++j) acc[i][j] = 0.f;

    for (int k0 = 0; k0 < NIN; k0 += BK) {
#pragma unroll
        for (int i = tid; i < BM * BK / 4; i += 256) {
            int m = i >> 2, kq = i & 3;
            float4 v = *(const float4*)(A + (long)(m0 + m) * NIN + k0 + kq * 4);
            As[kq * 4 + 0][m] = v.x;
            As[kq * 4 + 1][m] = v.y;
            As[kq * 4 + 2][m] = v.z;
            As[kq * 4 + 3][m] = v.w;
        }
#pragma unroll
        for (int i = tid; i < BK * BN / 4; i += 256) {
            int kk = i >> 4, nq = i & 15;
            *(float4*)(&Bs[kk][nq * 4]) =
                *(const float4*)(Bm + (long)(k0 + kk) * NH + n0 + nq * 4);
        }
        __syncthreads();

#pragma unroll
        for (int kk = 0; kk < BK; ++kk) {
            float4 a4 = *(const float4*)(&As[kk][ty * 4]);
            float4 b4 = *(const float4*)(&Bs[kk][tx * 4]);
            acc[0][0] = fmaf(a4.x, b4.x, acc[0][0]);
            acc[0][1] = fmaf(a4.x, b4.y, acc[0][1]);
            acc[0][2] = fmaf(a4.x, b4.z, acc[0][2]);
            acc[0][3] = fmaf(a4.x, b4.w, acc[0][3]);
            acc[1][0] = fmaf(a4.y, b4.x, acc[1][0]);
            acc[1][1] = fmaf(a4.y, b4.y, acc[1][1]);
            acc[1][2] = fmaf(a4.y, b4.z, acc[1][2]);
            acc[1][3] = fmaf(a4.y, b4.w, acc[1][3]);
            acc[2][0] = fmaf(a4.z, b4.x, acc[2][0]);
            acc[2][1] = fmaf(a4.z, b4.y, acc[2][1]);
            acc[2][2] = fmaf(a4.z, b4.z, acc[2][2]);
            acc[2][3] = fmaf(a4.z, b4.w, acc[2][3]);
            acc[3][0] = fmaf(a4.w, b4.x, acc[3][0]);
            acc[3][1] = fmaf(a4.w, b4.y, acc[3][1]);
            acc[3][2] = fmaf(a4.w, b4.z, acc[3][2]);
            acc[3][3] = fmaf(a4.w, b4.w, acc[3][3]);
        }
        __syncthreads();
    }

#pragma unroll
    for (int i = 0; i < 4; ++i) {
        const int m = m0 + ty * 4 + i;
#pragma unroll
        for (int j = 0; j < 4; ++j) {
            const int n = n0 + tx * 4 + j;
            C[(long)m * NH + n] = acc[i][j] + bias[n];
        }
    }
}

// ---------------- Phase B: persistent recurrent kernel ----------------------
// 128 CTAs = 4 batch-groups (16 batches) x 32 col-groups (16 cols), 512 thr.
// Per-producer release flags / acquire polls; warp kt polls only its 2
// producers (cgrp 2kt, 2kt+1), stages its 2KB k-slice with VOLATILE loads
// (cannot be hoisted above the poll), computes with FFMA2. CTA-wide sync only
// around the fold; buf[t&1] write is WAR-safe because it happens after all 16
// warps observed all 32 flags >= t-1.

__global__ __launch_bounds__(NTHB, 1) void step_kernel(
    const float* __restrict__ W_hid,
    const float* __restrict__ b_hid,
    const float* __restrict__ alpha,
    const float* __restrict__ init_state,
    float* __restrict__ out) {
    extern __shared__ float sh[];
    uint64_t* wd  = (uint64_t*)sh;        // [512][16] u64: wd[k*16+c] = {w,w}
    float*    frs = sh + SM_FRS;          // [16 kt][32 k][16 b]
    float*    red = sh + SM_RED;          // [16 kt][16 c][RB]

    const int tid  = threadIdx.x;
    const int bgrp = blockIdx.x >> 5;     // 0..3
    const int cgrp = blockIdx.x & 31;     // 0..31
    const int B0   = bgrp * 16;
    const int C0   = cgrp * 16;

    // compute roles: warp = kt, lanes = (bg, cg)
    const int kt   = tid >> 5;            // 0..15 (32 k each)
    const int lane = tid & 31;
    const int bg   = (tid >> 3) & 3;      // 0..3  (4 batches)
    const int cg   = tid & 7;             // 0..7  (2 cols)
    // fold roles (tid < 256)
    const int ec = tid & 15;
    const int eb = (tid >> 4) & 15;
    const int gb = B0 + eb;
    const int gc = C0 + ec;

    // ---- one-time: W slice as duplicated pairs ----
    for (int i = tid; i < NH * 16; i += NTHB) {
        int k = i >> 4, c = i & 15;
        float w = W_hid[(long)k * NH + C0 + c];
        wd[i] = pk2(w, w);
    }

    // ---- warp-local fr(0) slice from init_state (no exchange) ----
    {
        float* dst = frs + kt * 512;      // [32 k][16 b]
#pragma unroll
        for (int j = 0; j < 4; ++j) {
            int fidx = j * 32 + lane;     // 0..127 float4s
            int kl = fidx >> 2, q = fidx & 3;
            int k = kt * 32 + kl;
            float4 vv;
            vv.x = fmaxf(init_state[(long)(B0 + q * 4 + 0) * NH + k], 0.f);
            vv.y = fmaxf(init_state[(long)(B0 + q * 4 + 1) * NH + k], 0.f);
            vv.z = fmaxf(init_state[(long)(B0 + q * 4 + 2) * NH + k], 0.f);
            vv.w = fmaxf(init_state[(long)(B0 + q * 4 + 3) * NH + k], 0.f);
            *(float4*)(dst + fidx * 4) = vv;
        }
    }

    float v = 0.f, al = 0.f, bh = 0.f, oma = 0.f;
    if (tid < 256) {
        v   = init_state[(long)gb * NH + gc];
        al  = alpha[gc];
        bh  = b_hid[gc];
        oma = 1.f - al;
    }
    __syncthreads();   // wd + frs(t=0) ready

    const float*    fp0   = frs + kt * 512 + bg * 4;
    const uint64_t* wp0   = wd + (kt * 32) * 16 + cg * 2;
    const unsigned* flagA = &g_flags2[bgrp][2 * kt][0];
    const unsigned* flagB = &g_flags2[bgrp][2 * kt + 1][0];

    for (int t = 1; t <= NT; ++t) {
        long  oidx = 0;
        float vin  = 0.f;
        if (tid < 256) {
            oidx = ((long)gb * NT + (t - 1)) * NH + gc;
            vin  = out[oidx];                         // DRAM prefetch
        }

        if (t >= 2) {
            // ---- per-warp: lanes 0/1 acquire-poll the 2 producers ----
            const unsigned tgt = (unsigned)(t - 1);
            if (lane == 0) { while (ld_acq(flagA) < tgt) { } }
            if (lane == 1) { while (ld_acq(flagB) < tgt) { } }
            __syncwarp();

            // ---- stage my 2KB k-slice (volatile loads: no hoist) ----
            const float* src = &g_fr2[(t - 1) & 1][bgrp][kt * 32][0];
            float*       dst = frs + kt * 512;
#pragma unroll
            for (int j = 0; j < 4; ++j) {
                int fidx = j * 32 + lane;
                float4 vv = ldcg_v4((const float4*)src + fidx);
                *(float4*)(dst + fidx * 4) = vv;
            }
            __syncwarp();
        }

        // ---- inner GEMM: 32 kk x (2 LDS.128 + 4 FFMA2) ----
        uint64_t a00 = 0, a10 = 0, a01 = 0, a11 = 0;
#pragma unroll
        for (int kk = 0; kk < 32; ++kk) {
            ulonglong2 fv = *(const ulonglong2*)(fp0 + kk * 16);  // {b0,b1},{b2,b3}
            ulonglong2 wv = *(const ulonglong2*)(wp0 + kk * 16);  // {c0,c0},{c1,c1}
            a00 = fma2(fv.x, wv.x, a00);
            a10 = fma2(fv.y, wv.x, a10);
            a01 = fma2(fv.x, wv.y, a01);
            a11 = fma2(fv.y, wv.y, a11);
        }

        // ---- publish kt-partials ----
        {
            float* rp = red + kt * RC + (cg * 2) * RB + bg * 4;
            ulonglong2 s0; s0.x = a00; s0.y = a10;
            ulonglong2 s1; s1.x = a01; s1.y = a11;
            *(ulonglong2*)rp        = s0;
            *(ulonglong2*)(rp + RB) = s1;
        }
        __syncthreads();

        // ---- fold 16 partials + leaky update (thread owns (eb,ec)) ----
        if (tid < 256) {
            const float* rr = red + ec * RB + eb;
            float s0 = rr[0 * RC]  + rr[1 * RC];
            float s1 = rr[2 * RC]  + rr[3 * RC];
            float s2 = rr[4 * RC]  + rr[5 * RC];
            float s3 = rr[6 * RC]  + rr[7 * RC];
            float s4 = rr[8 * RC]  + rr[9 * RC];
            float s5 = rr[10 * RC] + rr[11 * RC];
            float s6 = rr[12 * RC] + rr[13 * RC];
            float s7 = rr[14 * RC] + rr[15 * RC];
            float s  = ((s0 + s1) + (s2 + s3)) + ((s4 + s5) + (s6 + s7));

            v = oma * v + al * (s + bh + vin);
            const float fr = fmaxf(v, 0.f);
            __stcg(&g_fr2[t & 1][bgrp][gc][eb], fr);
            out[oidx] = fr;
            __threadfence();   // each data-writing thread: gpu-scope ordering
        }
        __syncthreads();       // red WAR + all data stores fenced

        // ---- publish flag with RELEASE (no consumers after last step) ----
        if (t < NT && tid == 0) {
            st_rel(&g_flags2[bgrp][cgrp][0], (unsigned)t);
        }
    }
}

// ---------------- launch ----------------------------------------------------
extern "C" void kernel_launch(void* const* d_in, const int* in_sizes, int n_in,
                              void* d_out, int out_size) {
    const float* x     = (const float*)d_in[0];
    const float* init  = (const float*)d_in[1];
    const float* W_in  = (const float*)d_in[2];
    const float* b_in  = (const float*)d_in[3];
    const float* W_hid = (const float*)d_in[4];
    const float* b_hid = (const float*)d_in[5];
    const float* alpha = (const float*)d_in[6];
    float* out = (float*)d_out;

    cudaFuncSetAttribute(step_kernel,
                         cudaFuncAttributeMaxDynamicSharedMemorySize, SMEM_BYTES);

    init_kernel<<<8, 512>>>();             // zero 4096 flag words every replay

    dim3 grid(NH / BN, (NB * NT) / BM);    // (8, 1024)
    gemm_vin<<<grid, 256>>>(x, W_in, b_in, out);

    step_kernel<<<NCTA, NTHB, SMEM_BYTES>>>(W_hid, b_hid, alpha, init, out);
}